// round 8
// baseline (speedup 1.0000x reference)
#include <cuda_runtime.h>

#define N_NODES 100000
#define IN_C    128
#define HC      256
#define NHEAD   4
#define CDIM    64
#define NE      1600000
#define NEG     0.2f
#define BNEPS   1e-5f

// ---- device scratch (allocation-free: __device__ globals) ----
__device__ float g_h[N_NODES * HC];          // projected features  [N,256]
__device__ float g_asrc[N_NODES * NHEAD];    // per-node src logits [N,4]
__device__ float g_adst[N_NODES * NHEAD];    // per-node dst logits [N,4]
__device__ int   g_cnt[N_NODES];             // in-degree histogram
__device__ int   g_rowptr[N_NODES + 1];      // CSR row pointers (by dst)
__device__ int   g_fill[N_NODES];            // fill cursors
__device__ int   g_csr[NE];                  // src ids grouped by dst
__device__ int   g_part[128];                // scan partials
__device__ int   g_part2[128];
__device__ float g_stat[2 * HC];             // per-channel sum / sumsq
__device__ float g_scale[HC];
__device__ float g_shift[HC];
__device__ int   g_i64;                      // 1 if edge_index is int64

// ---------------------------------------------------------------------------
// Probe edge_index dtype: if the buffer is int64 (values < 2^31), every odd
// int32 word is 0.
__global__ void probe_kernel(const int* __restrict__ ei32) {
    int v = 0;
    for (int k = 0; k < 1024; k++) v |= ei32[2 * k + 1];
    g_i64 = (v == 0) ? 1 : 0;
}

__device__ __forceinline__ int load_edge(const void* ei, int idx) {
    if (g_i64) return (int)((const long long*)ei)[idx];
    return ((const int*)ei)[idx];
}

// ---------------------------------------------------------------------------
__global__ void init_kernel() {
    int i = blockIdx.x * blockDim.x + threadIdx.x;
    if (i < N_NODES) g_cnt[i] = 0;
    if (i < 2 * HC)  g_stat[i] = 0.f;
}

// ---------------------------------------------------------------------------
// GEMM: g_h = x @ W   (100000x128 @ 128x256), 64x256 block tile, 8x8 thread
// tile. Epilogue computes a_src/a_dst from register-resident accumulators:
// thread covers cols tx*8..tx*8+7 which map to att[tx*8+j]; 8-lane segmented
// shuffle reduce gives the per-(row,head) dot.
__global__ __launch_bounds__(256) void gemm_kernel(const float* __restrict__ x,
                                                   const float* __restrict__ W,
                                                   const float* __restrict__ att_src,
                                                   const float* __restrict__ att_dst) {
    __shared__ float Ws[16][256];
    __shared__ float Xs[16][64];
    const int rowbase = blockIdx.x * 64;
    const int tid = threadIdx.x;
    const int ty = tid >> 5;      // warp id 0..7  -> row group
    const int tx = tid & 31;      // lane          -> col group
    float acc[8][8] = {};

    for (int k0 = 0; k0 < IN_C; k0 += 16) {
        #pragma unroll
        for (int i = 0; i < 4; i++) {
            int idx = tid + i * 256;          // float4 index
            int k = idx >> 6, c4 = idx & 63;
            float4 w = *(const float4*)(W + (k0 + k) * 256 + c4 * 4);
            *(float4*)(&Ws[k][c4 * 4]) = w;
        }
        {
            int r = tid >> 2, kq = tid & 3;
            int row = rowbase + r;
            float4 xv = make_float4(0.f, 0.f, 0.f, 0.f);
            if (row < N_NODES)
                xv = *(const float4*)(x + row * IN_C + k0 + kq * 4);
            Xs[kq * 4 + 0][r] = xv.x; Xs[kq * 4 + 1][r] = xv.y;
            Xs[kq * 4 + 2][r] = xv.z; Xs[kq * 4 + 3][r] = xv.w;
        }
        __syncthreads();
        #pragma unroll
        for (int k = 0; k < 16; k++) {
            float xf[8], wf[8];
            *(float4*)(xf)     = *(float4*)&Xs[k][ty * 8];
            *(float4*)(xf + 4) = *(float4*)&Xs[k][ty * 8 + 4];
            *(float4*)(wf)     = *(float4*)&Ws[k][tx * 8];
            *(float4*)(wf + 4) = *(float4*)&Ws[k][tx * 8 + 4];
            #pragma unroll
            for (int i = 0; i < 8; i++)
                #pragma unroll
                for (int j = 0; j < 8; j++)
                    acc[i][j] += xf[i] * wf[j];
        }
        __syncthreads();
    }

    // attention vectors for this thread's 8 columns (flat index == tx*8+j)
    float ats[8], atd[8];
    *(float4*)(ats)     = *(const float4*)(att_src + tx * 8);
    *(float4*)(ats + 4) = *(const float4*)(att_src + tx * 8 + 4);
    *(float4*)(atd)     = *(const float4*)(att_dst + tx * 8);
    *(float4*)(atd + 4) = *(const float4*)(att_dst + tx * 8 + 4);
    const int head = tx >> 3;

    #pragma unroll
    for (int i = 0; i < 8; i++) {
        int row = rowbase + ty * 8 + i;
        if (row < N_NODES) {
            *(float4*)(g_h + row * 256 + tx * 8) =
                make_float4(acc[i][0], acc[i][1], acc[i][2], acc[i][3]);
            *(float4*)(g_h + row * 256 + tx * 8 + 4) =
                make_float4(acc[i][4], acc[i][5], acc[i][6], acc[i][7]);
        }
        float as = 0.f, ad = 0.f;
        #pragma unroll
        for (int j = 0; j < 8; j++) {
            as += acc[i][j] * ats[j];
            ad += acc[i][j] * atd[j];
        }
        #pragma unroll
        for (int o = 4; o; o >>= 1) {
            as += __shfl_down_sync(0xFFFFFFFFu, as, o, 8);
            ad += __shfl_down_sync(0xFFFFFFFFu, ad, o, 8);
        }
        if ((tx & 7) == 0 && row < N_NODES) {
            g_asrc[row * 4 + head] = as;
            g_adst[row * 4 + head] = ad;
        }
    }
}

// ---------------------------------------------------------------------------
__global__ void hist_kernel(const void* __restrict__ ei) {
    int i = blockIdx.x * blockDim.x + threadIdx.x;
    if (i < NE) {
        int d = load_edge(ei, NE + i);
        if ((unsigned)d < (unsigned)N_NODES) atomicAdd(&g_cnt[d], 1);
    }
}

__global__ __launch_bounds__(1024) void scan1_kernel() {
    __shared__ int sh[1024];
    int i = blockIdx.x * 1024 + threadIdx.x;
    int v = (i < N_NODES) ? g_cnt[i] : 0;
    sh[threadIdx.x] = v; __syncthreads();
    for (int off = 1; off < 1024; off <<= 1) {
        int t = (threadIdx.x >= off) ? sh[threadIdx.x - off] : 0;
        __syncthreads();
        sh[threadIdx.x] += t; __syncthreads();
    }
    if (i < N_NODES) g_rowptr[i] = sh[threadIdx.x] - v;  // exclusive
    if (threadIdx.x == 1023) g_part[blockIdx.x] = sh[1023];
}

__global__ __launch_bounds__(128) void scan2_kernel(int nb) {
    __shared__ int sh[128];
    int v = (threadIdx.x < nb) ? g_part[threadIdx.x] : 0;
    sh[threadIdx.x] = v; __syncthreads();
    for (int off = 1; off < 128; off <<= 1) {
        int t = (threadIdx.x >= off) ? sh[threadIdx.x - off] : 0;
        __syncthreads();
        sh[threadIdx.x] += t; __syncthreads();
    }
    if (threadIdx.x < nb) g_part2[threadIdx.x] = sh[threadIdx.x] - v;
    if (threadIdx.x == nb - 1) g_rowptr[N_NODES] = sh[threadIdx.x]; // total valid
}

__global__ __launch_bounds__(1024) void scan3_kernel() {
    int i = blockIdx.x * 1024 + threadIdx.x;
    if (i < N_NODES) {
        int v = g_rowptr[i] + g_part2[blockIdx.x];
        g_rowptr[i] = v;
        g_fill[i] = v;
    }
}

__global__ void fill_kernel(const void* __restrict__ ei) {
    int i = blockIdx.x * blockDim.x + threadIdx.x;
    if (i < NE) {
        int s = load_edge(ei, i);
        int d = load_edge(ei, NE + i);
        if ((unsigned)s < (unsigned)N_NODES && (unsigned)d < (unsigned)N_NODES) {
            int pos = atomicAdd(&g_fill[d], 1);
            g_csr[pos] = s;
        }
    }
}

// ---------------------------------------------------------------------------
// per-destination-node softmax + weighted aggregate. One block per node,
// thread t owns channel t -> every h[src] gather is a coalesced 1KB row read.
// Denominators: register accumulation + warp reduce (no contended atomics).
__global__ __launch_bounds__(256) void agg_kernel(const float* __restrict__ bias,
                                                  float* __restrict__ out) {
    const int i = blockIdx.x;
    const int tid = threadIdx.x;
    const int lane = tid & 31;
    __shared__ float sden[4];
    __shared__ int   ssrc[64];
    __shared__ float sal[64][4];

    const int ebase = g_rowptr[i];
    const int deg = g_rowptr[i + 1] - ebase;

    if (tid < 4) sden[tid] = 0.f;

    const float4 ad = *(const float4*)(g_adst + i * 4);   // broadcast
    const float4 asI = *(const float4*)(g_asrc + i * 4);  // broadcast (self)

    // self-loop exps (every thread computes all 4; cheap)
    float ex0, ex1, ex2, ex3, e;
    e = asI.x + ad.x; e = e > 0.f ? e : NEG * e; ex0 = __expf(e);
    e = asI.y + ad.y; e = e > 0.f ? e : NEG * e; ex1 = __expf(e);
    e = asI.z + ad.z; e = e > 0.f ? e : NEG * e; ex2 = __expf(e);
    e = asI.w + ad.w; e = e > 0.f ? e : NEG * e; ex3 = __expf(e);
    __syncthreads();

    // denominator pass: one edge per thread, 4 heads in registers
    float d0 = 0.f, d1 = 0.f, d2 = 0.f, d3 = 0.f;
    for (int j = tid; j < deg; j += 256) {
        int s = g_csr[ebase + j];
        float4 a = *(const float4*)(g_asrc + s * 4);
        e = a.x + ad.x; e = e > 0.f ? e : NEG * e; d0 += __expf(e);
        e = a.y + ad.y; e = e > 0.f ? e : NEG * e; d1 += __expf(e);
        e = a.z + ad.z; e = e > 0.f ? e : NEG * e; d2 += __expf(e);
        e = a.w + ad.w; e = e > 0.f ? e : NEG * e; d3 += __expf(e);
    }
    #pragma unroll
    for (int o = 16; o; o >>= 1) {
        d0 += __shfl_xor_sync(0xFFFFFFFFu, d0, o);
        d1 += __shfl_xor_sync(0xFFFFFFFFu, d1, o);
        d2 += __shfl_xor_sync(0xFFFFFFFFu, d2, o);
        d3 += __shfl_xor_sync(0xFFFFFFFFu, d3, o);
    }
    if (lane == 0) {
        if (tid == 0) { d0 += ex0; d1 += ex1; d2 += ex2; d3 += ex3; } // self
        atomicAdd(&sden[0], d0);
        atomicAdd(&sden[1], d1);
        atomicAdd(&sden[2], d2);
        atomicAdd(&sden[3], d3);
    }
    __syncthreads();

    float inv0 = 1.f / (sden[0] + 1e-16f);
    float inv1 = 1.f / (sden[1] + 1e-16f);
    float inv2 = 1.f / (sden[2] + 1e-16f);
    float inv3 = 1.f / (sden[3] + 1e-16f);

    const int hd = tid >> 6;
    const float selfw = (hd == 0) ? ex0 * inv0 : (hd == 1) ? ex1 * inv1
                      : (hd == 2) ? ex2 * inv2 : ex3 * inv3;
    float a0 = g_h[i * 256 + tid] * selfw;   // self-loop contribution
    float a1 = 0.f, a2 = 0.f, a3 = 0.f, a4 = 0.f, a5 = 0.f, a6 = 0.f, a7 = 0.f;

    for (int base = 0; base < deg; base += 64) {
        int m = min(64, deg - base);
        if (tid < m) {
            int s = g_csr[ebase + base + tid];
            ssrc[tid] = s;
            float4 a = *(const float4*)(g_asrc + s * 4);
            float4 w;
            e = a.x + ad.x; e = e > 0.f ? e : NEG * e; w.x = __expf(e) * inv0;
            e = a.y + ad.y; e = e > 0.f ? e : NEG * e; w.y = __expf(e) * inv1;
            e = a.z + ad.z; e = e > 0.f ? e : NEG * e; w.z = __expf(e) * inv2;
            e = a.w + ad.w; e = e > 0.f ? e : NEG * e; w.w = __expf(e) * inv3;
            *(float4*)&sal[tid][0] = w;
        }
        __syncthreads();
        int j = 0;
        for (; j + 8 <= m; j += 8) {   // 8-way MLP for latency hiding
            int s0 = ssrc[j],     s1 = ssrc[j + 1], s2 = ssrc[j + 2], s3 = ssrc[j + 3];
            int s4 = ssrc[j + 4], s5 = ssrc[j + 5], s6 = ssrc[j + 6], s7 = ssrc[j + 7];
            a0 += g_h[s0 * 256 + tid] * sal[j][hd];
            a1 += g_h[s1 * 256 + tid] * sal[j + 1][hd];
            a2 += g_h[s2 * 256 + tid] * sal[j + 2][hd];
            a3 += g_h[s3 * 256 + tid] * sal[j + 3][hd];
            a4 += g_h[s4 * 256 + tid] * sal[j + 4][hd];
            a5 += g_h[s5 * 256 + tid] * sal[j + 5][hd];
            a6 += g_h[s6 * 256 + tid] * sal[j + 6][hd];
            a7 += g_h[s7 * 256 + tid] * sal[j + 7][hd];
        }
        for (; j < m; j++)
            a0 += g_h[ssrc[j] * 256 + tid] * sal[j][hd];
        __syncthreads();
    }
    out[i * 256 + tid] = ((a0 + a1) + (a2 + a3)) + ((a4 + a5) + (a6 + a7)) + bias[tid];
}

// ---------------------------------------------------------------------------
__global__ __launch_bounds__(256) void bnstat_kernel(const float* __restrict__ out) {
    int t = threadIdx.x;
    int r0 = blockIdx.x * 64;
    int rmax = min(64, N_NODES - r0);
    float s = 0.f, s2 = 0.f;
    for (int r = 0; r < rmax; r++) {
        float v = out[(size_t)(r0 + r) * 256 + t];
        s += v; s2 += v * v;
    }
    atomicAdd(&g_stat[t], s);
    atomicAdd(&g_stat[256 + t], s2);
}

__global__ __launch_bounds__(256) void bnfin_kernel(const float* __restrict__ gamma,
                                                    const float* __restrict__ beta) {
    int t = threadIdx.x;
    float invN = 1.f / (float)N_NODES;
    float mean = g_stat[t] * invN;
    float var = g_stat[256 + t] * invN - mean * mean;
    float sc = gamma[t] * rsqrtf(var + BNEPS);
    g_scale[t] = sc;
    g_shift[t] = beta[t] - mean * sc;
}

__global__ __launch_bounds__(256) void final_kernel(float* __restrict__ out) {
    int i4 = blockIdx.x * 256 + threadIdx.x;             // float4 index
    if (i4 >= N_NODES * (HC / 4)) return;
    int c = (i4 & 63) * 4;
    float4 v = ((float4*)out)[i4];
    float f;
    f = g_scale[c + 0] * v.x + g_shift[c + 0]; v.x = f > 0.f ? f : expm1f(f);
    f = g_scale[c + 1] * v.y + g_shift[c + 1]; v.y = f > 0.f ? f : expm1f(f);
    f = g_scale[c + 2] * v.z + g_shift[c + 2]; v.z = f > 0.f ? f : expm1f(f);
    f = g_scale[c + 3] * v.w + g_shift[c + 3]; v.w = f > 0.f ? f : expm1f(f);
    ((float4*)out)[i4] = v;
}

// ---------------------------------------------------------------------------
extern "C" void kernel_launch(void* const* d_in, const int* in_sizes, int n_in,
                              void* d_out, int out_size) {
    const float* x       = (const float*)d_in[0];
    const void*  ei      = d_in[1];
    const float* W       = (const float*)d_in[2];
    const float* att_src = (const float*)d_in[3];
    const float* att_dst = (const float*)d_in[4];
    const float* bias    = (const float*)d_in[5];
    const float* gamma   = (const float*)d_in[6];
    const float* beta    = (const float*)d_in[7];
    float* out = (float*)d_out;

    probe_kernel<<<1, 1>>>((const int*)ei);
    init_kernel<<<(N_NODES + 255) / 256, 256>>>();

    hist_kernel<<<(NE + 255) / 256, 256>>>(ei);
    gemm_kernel<<<(N_NODES + 63) / 64, 256>>>(x, W, att_src, att_dst);

    int nb = (N_NODES + 1023) / 1024;   // 98
    scan1_kernel<<<nb, 1024>>>();
    scan2_kernel<<<1, 128>>>(nb);
    scan3_kernel<<<nb, 1024>>>();
    fill_kernel<<<(NE + 255) / 256, 256>>>(ei);

    agg_kernel<<<N_NODES, 256>>>(bias, out);

    bnstat_kernel<<<(N_NODES + 63) / 64, 256>>>(out);
    bnfin_kernel<<<1, 256>>>(gamma, beta);
    final_kernel<<<(N_NODES * (HC / 4) + 255) / 256, 256>>>(out);
}

// round 9
// speedup vs baseline: 1.4303x; 1.4303x over previous
#include <cuda_runtime.h>

#define N_NODES 100000
#define IN_C    128
#define HC      256
#define NHEAD   4
#define CDIM    64
#define NE      1600000
#define NEG     0.2f
#define BNEPS   1e-5f

// ---- device scratch (allocation-free: __device__ globals) ----
__device__ float g_h[N_NODES * HC];          // projected features  [N,256]
__device__ float g_asrc[N_NODES * NHEAD];    // per-node src logits [N,4]
__device__ float g_adst[N_NODES * NHEAD];    // per-node dst logits [N,4]
__device__ int   g_cnt[N_NODES];             // in-degree histogram
__device__ int   g_rowptr[N_NODES + 1];      // CSR row pointers (by dst)
__device__ int   g_fill[N_NODES];            // fill cursors
__device__ int   g_csr[NE];                  // src ids grouped by dst
__device__ int   g_part[128];                // scan partials
__device__ int   g_part2[128];
__device__ float g_stat[2 * HC];             // per-channel sum / sumsq
__device__ float g_scale[HC];
__device__ float g_shift[HC];
__device__ int   g_i64;                      // 1 if edge_index is int64

// ---------------------------------------------------------------------------
__global__ void probe_kernel(const int* __restrict__ ei32) {
    int v = 0;
    for (int k = 0; k < 1024; k++) v |= ei32[2 * k + 1];
    g_i64 = (v == 0) ? 1 : 0;
}

__device__ __forceinline__ int load_edge(const void* ei, int idx) {
    if (g_i64) return (int)((const long long*)ei)[idx];
    return ((const int*)ei)[idx];
}

// ---------------------------------------------------------------------------
__global__ void init_kernel() {
    int i = blockIdx.x * blockDim.x + threadIdx.x;
    if (i < N_NODES) g_cnt[i] = 0;
    if (i < 2 * HC)  g_stat[i] = 0.f;
}

// ---------------------------------------------------------------------------
// GEMM: g_h = x @ W (100000x128 @ 128x256), 64x256 block tile, 8x8 thread
// tile, fused a_src/a_dst epilogue (8-lane segmented shuffle reduce).
__global__ __launch_bounds__(256) void gemm_kernel(const float* __restrict__ x,
                                                   const float* __restrict__ W,
                                                   const float* __restrict__ att_src,
                                                   const float* __restrict__ att_dst) {
    __shared__ float Ws[16][256];
    __shared__ float Xs[16][64];
    const int rowbase = blockIdx.x * 64;
    const int tid = threadIdx.x;
    const int ty = tid >> 5;
    const int tx = tid & 31;
    float acc[8][8] = {};

    for (int k0 = 0; k0 < IN_C; k0 += 16) {
        #pragma unroll
        for (int i = 0; i < 4; i++) {
            int idx = tid + i * 256;
            int k = idx >> 6, c4 = idx & 63;
            float4 w = *(const float4*)(W + (k0 + k) * 256 + c4 * 4);
            *(float4*)(&Ws[k][c4 * 4]) = w;
        }
        {
            int r = tid >> 2, kq = tid & 3;
            int row = rowbase + r;
            float4 xv = make_float4(0.f, 0.f, 0.f, 0.f);
            if (row < N_NODES)
                xv = *(const float4*)(x + row * IN_C + k0 + kq * 4);
            Xs[kq * 4 + 0][r] = xv.x; Xs[kq * 4 + 1][r] = xv.y;
            Xs[kq * 4 + 2][r] = xv.z; Xs[kq * 4 + 3][r] = xv.w;
        }
        __syncthreads();
        #pragma unroll
        for (int k = 0; k < 16; k++) {
            float xf[8], wf[8];
            *(float4*)(xf)     = *(float4*)&Xs[k][ty * 8];
            *(float4*)(xf + 4) = *(float4*)&Xs[k][ty * 8 + 4];
            *(float4*)(wf)     = *(float4*)&Ws[k][tx * 8];
            *(float4*)(wf + 4) = *(float4*)&Ws[k][tx * 8 + 4];
            #pragma unroll
            for (int i = 0; i < 8; i++)
                #pragma unroll
                for (int j = 0; j < 8; j++)
                    acc[i][j] += xf[i] * wf[j];
        }
        __syncthreads();
    }

    float ats[8], atd[8];
    *(float4*)(ats)     = *(const float4*)(att_src + tx * 8);
    *(float4*)(ats + 4) = *(const float4*)(att_src + tx * 8 + 4);
    *(float4*)(atd)     = *(const float4*)(att_dst + tx * 8);
    *(float4*)(atd + 4) = *(const float4*)(att_dst + tx * 8 + 4);
    const int head = tx >> 3;

    #pragma unroll
    for (int i = 0; i < 8; i++) {
        int row = rowbase + ty * 8 + i;
        if (row < N_NODES) {
            *(float4*)(g_h + row * 256 + tx * 8) =
                make_float4(acc[i][0], acc[i][1], acc[i][2], acc[i][3]);
            *(float4*)(g_h + row * 256 + tx * 8 + 4) =
                make_float4(acc[i][4], acc[i][5], acc[i][6], acc[i][7]);
        }
        float as = 0.f, ad = 0.f;
        #pragma unroll
        for (int j = 0; j < 8; j++) {
            as += acc[i][j] * ats[j];
            ad += acc[i][j] * atd[j];
        }
        #pragma unroll
        for (int o = 4; o; o >>= 1) {
            as += __shfl_down_sync(0xFFFFFFFFu, as, o, 8);
            ad += __shfl_down_sync(0xFFFFFFFFu, ad, o, 8);
        }
        if ((tx & 7) == 0 && row < N_NODES) {
            g_asrc[row * 4 + head] = as;
            g_adst[row * 4 + head] = ad;
        }
    }
}

// ---------------------------------------------------------------------------
__global__ void hist_kernel(const void* __restrict__ ei) {
    int i = blockIdx.x * blockDim.x + threadIdx.x;
    if (i < NE) {
        int d = load_edge(ei, NE + i);
        if ((unsigned)d < (unsigned)N_NODES) atomicAdd(&g_cnt[d], 1);
    }
}

__global__ __launch_bounds__(1024) void scan1_kernel() {
    __shared__ int sh[1024];
    int i = blockIdx.x * 1024 + threadIdx.x;
    int v = (i < N_NODES) ? g_cnt[i] : 0;
    sh[threadIdx.x] = v; __syncthreads();
    for (int off = 1; off < 1024; off <<= 1) {
        int t = (threadIdx.x >= off) ? sh[threadIdx.x - off] : 0;
        __syncthreads();
        sh[threadIdx.x] += t; __syncthreads();
    }
    if (i < N_NODES) g_rowptr[i] = sh[threadIdx.x] - v;  // exclusive
    if (threadIdx.x == 1023) g_part[blockIdx.x] = sh[1023];
}

__global__ __launch_bounds__(128) void scan2_kernel(int nb) {
    __shared__ int sh[128];
    int v = (threadIdx.x < nb) ? g_part[threadIdx.x] : 0;
    sh[threadIdx.x] = v; __syncthreads();
    for (int off = 1; off < 128; off <<= 1) {
        int t = (threadIdx.x >= off) ? sh[threadIdx.x - off] : 0;
        __syncthreads();
        sh[threadIdx.x] += t; __syncthreads();
    }
    if (threadIdx.x < nb) g_part2[threadIdx.x] = sh[threadIdx.x] - v;
    if (threadIdx.x == nb - 1) g_rowptr[N_NODES] = sh[threadIdx.x]; // total valid
}

__global__ __launch_bounds__(1024) void scan3_kernel() {
    int i = blockIdx.x * 1024 + threadIdx.x;
    if (i < N_NODES) {
        int v = g_rowptr[i] + g_part2[blockIdx.x];
        g_rowptr[i] = v;
        g_fill[i] = v;
    }
}

__global__ void fill_kernel(const void* __restrict__ ei) {
    int i = blockIdx.x * blockDim.x + threadIdx.x;
    if (i < NE) {
        int s = load_edge(ei, i);
        int d = load_edge(ei, NE + i);
        if ((unsigned)s < (unsigned)N_NODES && (unsigned)d < (unsigned)N_NODES) {
            int pos = atomicAdd(&g_fill[d], 1);
            g_csr[pos] = s;
        }
    }
}

// ---------------------------------------------------------------------------
// Aggregate: one WARP per (node, head). 8 warps/block = 2 nodes. No shared
// memory, no block syncs. Each warp owns 64 channels (2 floats/lane); every
// feature gather is 2 contiguous 128B lines. Alphas are precomputed 32 edges
// at a time lane-parallel, then shuffled out; 4-edge MLP in the gather loop.
__global__ __launch_bounds__(256) void agg_kernel(const float* __restrict__ bias,
                                                  float* __restrict__ out) {
    const int warp = threadIdx.x >> 5;
    const int lane = threadIdx.x & 31;
    const int node = blockIdx.x * 2 + (warp >> 2);
    const int hd   = warp & 3;
    if (node >= N_NODES) return;

    const int ebase = g_rowptr[node];
    const int deg   = g_rowptr[node + 1] - ebase;
    const float adh = g_adst[node * 4 + hd];
    const int   off = hd * 64;

    // denominator (includes self-loop)
    float e = g_asrc[node * 4 + hd] + adh;
    e = e > 0.f ? e : NEG * e;
    const float exself = __expf(e);
    float den = (lane == 0) ? exself : 0.f;
    for (int j = lane; j < deg; j += 32) {
        int s = g_csr[ebase + j];
        float t = g_asrc[s * 4 + hd] + adh;
        t = t > 0.f ? t : NEG * t;
        den += __expf(t);
    }
    #pragma unroll
    for (int o = 16; o; o >>= 1) den += __shfl_xor_sync(0xFFFFFFFFu, den, o);
    const float inv = 1.f / (den + 1e-16f);

    // self contribution
    const float selfw = exself * inv;
    const float* hi = g_h + (size_t)node * 256 + off;
    float x0 = hi[lane] * selfw,       x1 = 0.f;
    float y0 = hi[lane + 32] * selfw,  y1 = 0.f;

    for (int base = 0; base < deg; base += 32) {
        const int m = min(32, deg - base);
        int   sl = 0; float al = 0.f;
        if (lane < m) {
            sl = g_csr[ebase + base + lane];
            float t = g_asrc[sl * 4 + hd] + adh;
            t = t > 0.f ? t : NEG * t;
            al = __expf(t) * inv;
        }
        int k = 0;
        for (; k + 4 <= m; k += 4) {
            int   s0 = __shfl_sync(0xFFFFFFFFu, sl, k);
            int   s1 = __shfl_sync(0xFFFFFFFFu, sl, k + 1);
            int   s2 = __shfl_sync(0xFFFFFFFFu, sl, k + 2);
            int   s3 = __shfl_sync(0xFFFFFFFFu, sl, k + 3);
            float w0 = __shfl_sync(0xFFFFFFFFu, al, k);
            float w1 = __shfl_sync(0xFFFFFFFFu, al, k + 1);
            float w2 = __shfl_sync(0xFFFFFFFFu, al, k + 2);
            float w3 = __shfl_sync(0xFFFFFFFFu, al, k + 3);
            const float* p0 = g_h + (size_t)s0 * 256 + off;
            const float* p1 = g_h + (size_t)s1 * 256 + off;
            const float* p2 = g_h + (size_t)s2 * 256 + off;
            const float* p3 = g_h + (size_t)s3 * 256 + off;
            x0 += p0[lane] * w0;  y0 += p0[lane + 32] * w0;
            x1 += p1[lane] * w1;  y1 += p1[lane + 32] * w1;
            x0 += p2[lane] * w2;  y0 += p2[lane + 32] * w2;
            x1 += p3[lane] * w3;  y1 += p3[lane + 32] * w3;
        }
        for (; k < m; k++) {
            int   s0 = __shfl_sync(0xFFFFFFFFu, sl, k);
            float w0 = __shfl_sync(0xFFFFFFFFu, al, k);
            const float* p0 = g_h + (size_t)s0 * 256 + off;
            x0 += p0[lane] * w0;  y0 += p0[lane + 32] * w0;
        }
    }
    float* po = out + (size_t)node * 256 + off;
    po[lane]      = x0 + x1 + bias[off + lane];
    po[lane + 32] = y0 + y1 + bias[off + lane + 32];
}

// ---------------------------------------------------------------------------
__global__ __launch_bounds__(256) void bnstat_kernel(const float* __restrict__ out) {
    int t = threadIdx.x;
    int r0 = blockIdx.x * 256;
    int rmax = min(256, N_NODES - r0);
    float s = 0.f, s2 = 0.f;
    for (int r = 0; r < rmax; r++) {
        float v = out[(size_t)(r0 + r) * 256 + t];
        s += v; s2 += v * v;
    }
    atomicAdd(&g_stat[t], s);
    atomicAdd(&g_stat[256 + t], s2);
}

__global__ __launch_bounds__(256) void bnfin_kernel(const float* __restrict__ gamma,
                                                    const float* __restrict__ beta) {
    int t = threadIdx.x;
    float invN = 1.f / (float)N_NODES;
    float mean = g_stat[t] * invN;
    float var = g_stat[256 + t] * invN - mean * mean;
    float sc = gamma[t] * rsqrtf(var + BNEPS);
    g_scale[t] = sc;
    g_shift[t] = beta[t] - mean * sc;
}

__global__ __launch_bounds__(256) void final_kernel(float* __restrict__ out) {
    int i4 = blockIdx.x * 256 + threadIdx.x;
    if (i4 >= N_NODES * (HC / 4)) return;
    int c = (i4 & 63) * 4;
    float4 v = ((float4*)out)[i4];
    float f;
    f = g_scale[c + 0] * v.x + g_shift[c + 0]; v.x = f > 0.f ? f : expm1f(f);
    f = g_scale[c + 1] * v.y + g_shift[c + 1]; v.y = f > 0.f ? f : expm1f(f);
    f = g_scale[c + 2] * v.z + g_shift[c + 2]; v.z = f > 0.f ? f : expm1f(f);
    f = g_scale[c + 3] * v.w + g_shift[c + 3]; v.w = f > 0.f ? f : expm1f(f);
    ((float4*)out)[i4] = v;
}

// ---------------------------------------------------------------------------
extern "C" void kernel_launch(void* const* d_in, const int* in_sizes, int n_in,
                              void* d_out, int out_size) {
    const float* x       = (const float*)d_in[0];
    const void*  ei      = d_in[1];
    const float* W       = (const float*)d_in[2];
    const float* att_src = (const float*)d_in[3];
    const float* att_dst = (const float*)d_in[4];
    const float* bias    = (const float*)d_in[5];
    const float* gamma   = (const float*)d_in[6];
    const float* beta    = (const float*)d_in[7];
    float* out = (float*)d_out;

    probe_kernel<<<1, 1>>>((const int*)ei);
    init_kernel<<<(N_NODES + 255) / 256, 256>>>();

    hist_kernel<<<(NE + 255) / 256, 256>>>(ei);
    gemm_kernel<<<(N_NODES + 63) / 64, 256>>>(x, W, att_src, att_dst);

    int nb = (N_NODES + 1023) / 1024;   // 98
    scan1_kernel<<<nb, 1024>>>();
    scan2_kernel<<<1, 128>>>(nb);
    scan3_kernel<<<nb, 1024>>>();
    fill_kernel<<<(NE + 255) / 256, 256>>>(ei);

    agg_kernel<<<(N_NODES + 1) / 2, 256>>>(bias, out);

    bnstat_kernel<<<(N_NODES + 255) / 256, 256>>>(out);
    bnfin_kernel<<<1, 256>>>(gamma, beta);
    final_kernel<<<(N_NODES * (HC / 4) + 255) / 256, 256>>>(out);
}